// round 1
// baseline (speedup 1.0000x reference)
#include <cuda_runtime.h>

#define HH 2048
#define WW 2048
#define HWN (HH*WW)
#define W4 (WW/4)
#define HW4 (HWN/4)
#define ROWS 8
#define SUB 8

// Scratch (device globals: allocation-free)
__device__ float4 g_immax[HW4];
__device__ float4 g_rmax[HW4];
__device__ double g_sums[4];      // 0:recon 1:r_smooth(raw, x255) 2:ismooth 3:eq
__device__ unsigned int g_hist[256];
__device__ int g_minbits;
__device__ int g_maxbits;

__global__ void k_zero() {
    int t = threadIdx.x;
    if (t < 256) g_hist[t] = 0u;
    if (t < 4) g_sums[t] = 0.0;
    if (t == 0) { g_minbits = 0x7F800000; g_maxbits = 0; }
}

// PIL 'L' grayscale on 8-bit quantized input; returns INTEGER gray value 0..255 as float.
// All intermediates are exact integers < 2^24 -> bit-identical to the jnp float path.
__device__ __forceinline__ float grayc(float r, float g, float b) {
    float q0 = floorf(__saturatef(r) * 255.0f);
    float q1 = floorf(__saturatef(g) * 255.0f);
    float q2 = floorf(__saturatef(b) * 255.0f);
    return floorf((q0 * 19595.0f + q1 * 38470.0f + q2 * 7471.0f + 32768.0f) * (1.0f / 65536.0f));
}

__global__ __launch_bounds__(256) void k1(const float4* __restrict__ in,
                                          const float4* __restrict__ Rp,
                                          const float4* __restrict__ Lp) {
    __shared__ float lut[256];           // exp(-10 * i / 255)
    __shared__ double redd[3][8];
    __shared__ float redf[2][8];
    for (int i = threadIdx.x; i < 256; i += blockDim.x)
        lut[i] = __expf((float)i * (-10.0f / 255.0f));
    __syncthreads();

    const int cx = blockIdx.x * blockDim.x + threadIdx.x;   // float4 column index
    const int r0 = blockIdx.y * ROWS;

    float4 gP, lP;                       // previous-row gray (integer-valued) and L
    if (r0 == 0) {
        gP = make_float4(0.f, 0.f, 0.f, 0.f);
        lP = gP;
    } else {                             // halo row r0-1
        int idx = (r0 - 1) * W4 + cx;
        float4 b0 = Rp[idx], b1 = Rp[idx + HW4], b2 = Rp[idx + 2 * HW4];
        gP.x = grayc(b0.x, b1.x, b2.x);
        gP.y = grayc(b0.y, b1.y, b2.y);
        gP.z = grayc(b0.z, b1.z, b2.z);
        gP.w = grayc(b0.w, b1.w, b2.w);
        lP = Lp[idx];
    }

    double sRec = 0.0, sRs = 0.0, sIs = 0.0;
    float vmin = 3.0f, vmax = -1.0f;

    #pragma unroll 2
    for (int rr = 0; rr < ROWS; rr++) {
        int idx = (r0 + rr) * W4 + cx;
        float4 a0 = in[idx], a1 = in[idx + HW4], a2 = in[idx + 2 * HW4];
        float4 b0 = Rp[idx], b1 = Rp[idx + HW4], b2 = Rp[idx + 2 * HW4];
        float4 lv = Lp[idx];

        // recon_low: sum |R*L - input| over 3 channels x 4 pixels
        float rec =
            fabsf(b0.x * lv.x - a0.x) + fabsf(b0.y * lv.y - a0.y) +
            fabsf(b0.z * lv.z - a0.z) + fabsf(b0.w * lv.w - a0.w) +
            fabsf(b1.x * lv.x - a1.x) + fabsf(b1.y * lv.y - a1.y) +
            fabsf(b1.z * lv.z - a1.z) + fabsf(b1.w * lv.w - a1.w) +
            fabsf(b2.x * lv.x - a2.x) + fabsf(b2.y * lv.y - a2.y) +
            fabsf(b2.z * lv.z - a2.z) + fabsf(b2.w * lv.w - a2.w);

        float4 im, rm, g;
        im.x = fmaxf(a0.x, fmaxf(a1.x, a2.x));
        im.y = fmaxf(a0.y, fmaxf(a1.y, a2.y));
        im.z = fmaxf(a0.z, fmaxf(a1.z, a2.z));
        im.w = fmaxf(a0.w, fmaxf(a1.w, a2.w));
        rm.x = fmaxf(b0.x, fmaxf(b1.x, b2.x));
        rm.y = fmaxf(b0.y, fmaxf(b1.y, b2.y));
        rm.z = fmaxf(b0.z, fmaxf(b1.z, b2.z));
        rm.w = fmaxf(b0.w, fmaxf(b1.w, b2.w));
        g_immax[idx] = im;
        g_rmax[idx] = rm;
        vmin = fminf(vmin, fminf(fminf(im.x, im.y), fminf(im.z, im.w)));
        vmax = fmaxf(vmax, fmaxf(fmaxf(im.x, im.y), fmaxf(im.z, im.w)));

        g.x = grayc(b0.x, b1.x, b2.x);
        g.y = grayc(b0.y, b1.y, b2.y);
        g.z = grayc(b0.z, b1.z, b2.z);
        g.w = grayc(b0.w, b1.w, b2.w);

        float rs = 0.f, is = 0.f;
        {
            float dg = fabsf(g.x - gP.x);
            rs += dg + 2.0f * g.x;
            is += fabsf(lv.x - lP.x) * lut[(int)dg] + 2.0f * fabsf(lv.x) * lut[(int)g.x];
        }
        {
            float dg = fabsf(g.y - gP.y);
            rs += dg + 2.0f * g.y;
            is += fabsf(lv.y - lP.y) * lut[(int)dg] + 2.0f * fabsf(lv.y) * lut[(int)g.y];
        }
        {
            float dg = fabsf(g.z - gP.z);
            rs += dg + 2.0f * g.z;
            is += fabsf(lv.z - lP.z) * lut[(int)dg] + 2.0f * fabsf(lv.z) * lut[(int)g.z];
        }
        {
            float dg = fabsf(g.w - gP.w);
            rs += dg + 2.0f * g.w;
            is += fabsf(lv.w - lP.w) * lut[(int)dg] + 2.0f * fabsf(lv.w) * lut[(int)g.w];
        }
        sRec += (double)rec;
        sRs  += (double)rs;
        sIs  += (double)is;
        gP = g;
        lP = lv;
    }

    // Bottom edge (i = H term of the padded conv): |0 - g|, |0 - L|*exp(-10*g/255)
    if (r0 + ROWS == HH) {
        float rs = gP.x + gP.y + gP.z + gP.w;
        float is = fabsf(lP.x) * lut[(int)gP.x] + fabsf(lP.y) * lut[(int)gP.y] +
                   fabsf(lP.z) * lut[(int)gP.z] + fabsf(lP.w) * lut[(int)gP.w];
        sRs += (double)rs;
        sIs += (double)is;
    }

    // Block reduce: 3 doubles + min/max
    const unsigned m = 0xffffffffu;
    for (int o = 16; o; o >>= 1) {
        sRec += __shfl_down_sync(m, sRec, o);
        sRs  += __shfl_down_sync(m, sRs,  o);
        sIs  += __shfl_down_sync(m, sIs,  o);
        vmin = fminf(vmin, __shfl_down_sync(m, vmin, o));
        vmax = fmaxf(vmax, __shfl_down_sync(m, vmax, o));
    }
    int lane = threadIdx.x & 31, wid = threadIdx.x >> 5;
    if (lane == 0) {
        redd[0][wid] = sRec; redd[1][wid] = sRs; redd[2][wid] = sIs;
        redf[0][wid] = vmin; redf[1][wid] = vmax;
    }
    __syncthreads();
    if (wid == 0) {
        sRec = (lane < 8) ? redd[0][lane] : 0.0;
        sRs  = (lane < 8) ? redd[1][lane] : 0.0;
        sIs  = (lane < 8) ? redd[2][lane] : 0.0;
        vmin = (lane < 8) ? redf[0][lane] : 3.0f;
        vmax = (lane < 8) ? redf[1][lane] : -1.0f;
        for (int o = 4; o; o >>= 1) {
            sRec += __shfl_down_sync(m, sRec, o);
            sRs  += __shfl_down_sync(m, sRs,  o);
            sIs  += __shfl_down_sync(m, sIs,  o);
            vmin = fminf(vmin, __shfl_down_sync(m, vmin, o));
            vmax = fmaxf(vmax, __shfl_down_sync(m, vmax, o));
        }
        if (lane == 0) {
            atomicAdd(&g_sums[0], sRec);
            atomicAdd(&g_sums[1], sRs);
            atomicAdd(&g_sums[2], sIs);
            atomicMin(&g_minbits, __float_as_int(vmin));  // all values >= 0
            atomicMax(&g_maxbits, __float_as_int(vmax));
        }
    }
}

__global__ __launch_bounds__(256) void k2() {
    __shared__ unsigned int h[256 * SUB];
    for (int i = threadIdx.x; i < 256 * SUB; i += 256) h[i] = 0u;
    __syncthreads();
    const float gmin = __int_as_float(g_minbits);
    const float gmax = __int_as_float(g_maxbits);
    const float scale = 256.0f / (gmax - gmin);
    const unsigned sub = threadIdx.x & (SUB - 1);
    for (int i = blockIdx.x * blockDim.x + threadIdx.x; i < HW4; i += gridDim.x * blockDim.x) {
        float4 v = g_immax[i];
        int k0 = min(255, (int)((v.x - gmin) * scale));
        int k1i = min(255, (int)((v.y - gmin) * scale));
        int k2i = min(255, (int)((v.z - gmin) * scale));
        int k3 = min(255, (int)((v.w - gmin) * scale));
        atomicAdd(&h[k0 * SUB + sub], 1u);
        atomicAdd(&h[k1i * SUB + sub], 1u);
        atomicAdd(&h[k2i * SUB + sub], 1u);
        atomicAdd(&h[k3 * SUB + sub], 1u);
    }
    __syncthreads();
    if (threadIdx.x < 256) {
        unsigned s = 0;
        #pragma unroll
        for (int j = 0; j < SUB; j++) s += h[threadIdx.x * SUB + j];
        if (s) atomicAdd(&g_hist[threadIdx.x], s);
    }
}

__device__ __forceinline__ float interp1(float x, float gmin, float scale, const float* cdf) {
    float u = (x - gmin) * scale;   // position in bin-width units; u in [0, 256]
    int k = (int)u;
    if (k >= 255) return cdf[255];
    float f = u - (float)k;
    return cdf[k] + (cdf[k + 1] - cdf[k]) * f;
}

__global__ __launch_bounds__(256) void k4() {
    __shared__ float cdf[256];
    __shared__ double redd[8];
    // inclusive scan of histogram counts (exact in float: total = 2^22)
    cdf[threadIdx.x] = (float)g_hist[threadIdx.x];
    __syncthreads();
    for (int off = 1; off < 256; off <<= 1) {
        float t = (threadIdx.x >= off) ? cdf[threadIdx.x - off] : 0.0f;
        __syncthreads();
        cdf[threadIdx.x] += t;
        __syncthreads();
    }
    float norm = cdf[255];
    __syncthreads();
    cdf[threadIdx.x] = cdf[threadIdx.x] / norm;
    __syncthreads();

    const float gmin = __int_as_float(g_minbits);
    const float gmax = __int_as_float(g_maxbits);
    const float scale = 256.0f / (gmax - gmin);
    double s = 0.0;
    for (int i = blockIdx.x * blockDim.x + threadIdx.x; i < HW4; i += gridDim.x * blockDim.x) {
        float4 v = g_immax[i];
        float4 r = g_rmax[i];
        float t = fabsf(r.x - interp1(v.x, gmin, scale, cdf))
                + fabsf(r.y - interp1(v.y, gmin, scale, cdf))
                + fabsf(r.z - interp1(v.z, gmin, scale, cdf))
                + fabsf(r.w - interp1(v.w, gmin, scale, cdf));
        s += (double)t;
    }
    const unsigned m = 0xffffffffu;
    for (int o = 16; o; o >>= 1) s += __shfl_down_sync(m, s, o);
    int lane = threadIdx.x & 31, wid = threadIdx.x >> 5;
    if (lane == 0) redd[wid] = s;
    __syncthreads();
    if (wid == 0) {
        s = (lane < 8) ? redd[lane] : 0.0;
        for (int o = 4; o; o >>= 1) s += __shfl_down_sync(m, s, o);
        if (lane == 0) atomicAdd(&g_sums[3], s);
    }
}

__global__ void k5(float* out) {
    double recon = g_sums[0] / (3.0 * (double)HWN);
    double denom = 2.0 * (double)(HH + 1) * (double)(WW + 2);
    double rs = g_sums[1] / (255.0 * denom);     // r_smooth (gray was integer units)
    double is = g_sums[2] / denom;               // ismooth
    double eq = g_sums[3] / (double)HWN;         // recon_low_eq
    out[0] = (float)(recon + 0.1 * is + 0.1 * eq + 0.01 * rs);
}

extern "C" void kernel_launch(void* const* d_in, const int* in_sizes, int n_in,
                              void* d_out, int out_size) {
    const float4* in = (const float4*)d_in[0];   // input_im [1,3,H,W]
    const float4* Rp = (const float4*)d_in[1];   // R        [1,3,H,W]
    const float4* Lp = (const float4*)d_in[2];   // L        [1,1,H,W]
    (void)in_sizes; (void)n_in; (void)out_size;

    k_zero<<<1, 256>>>();
    dim3 g1(W4 / 256, HH / ROWS);                // (2, 256) = 512 blocks
    k1<<<g1, 256>>>(in, Rp, Lp);
    k2<<<1184, 256>>>();
    k4<<<1184, 256>>>();
    k5<<<1, 1>>>((float*)d_out);
}

// round 2
// speedup vs baseline: 1.5873x; 1.5873x over previous
#include <cuda_runtime.h>
#include <cuda_fp16.h>

#define HH 2048
#define WW 2048
#define HWN (HH*WW)
#define W4 (WW/4)
#define HW4 (HWN/4)
#define NCTA 296
#define NTHR 512
#define MAXR 7
#define SUB 8

// dynamic smem layout (bytes):
//   s_im : MAXR*512 float4  = 57344
//   s_rm : MAXR*512 uint2   = 28672   (fp16x4 packed r_max)
//   s_lut: 256 float        = 1024
//   s_cdf: 256 float        = 1024
//   s_h  : 256*SUB uint     = 8192
#define SMEM_BYTES (MAXR*512*16 + MAXR*512*8 + 1024 + 1024 + 256*SUB*4)

__device__ double g_sums[4];      // 0:recon 1:r_smooth(x255) 2:ismooth 3:eq
__device__ unsigned int g_hist[256];
__device__ int g_minbits;
__device__ int g_maxbits;
__device__ unsigned int g_bar;

__global__ void k_zero() {
    int t = threadIdx.x;
    if (t < 256) g_hist[t] = 0u;
    if (t < 4) g_sums[t] = 0.0;
    if (t == 0) { g_minbits = 0x7F800000; g_maxbits = 0; g_bar = 0u; }
}

// PIL 'L' grayscale on 8-bit quantized input; returns INTEGER gray 0..255 as float.
__device__ __forceinline__ float grayc(float r, float g, float b) {
    float q0 = floorf(__saturatef(r) * 255.0f);
    float q1 = floorf(__saturatef(g) * 255.0f);
    float q2 = floorf(__saturatef(b) * 255.0f);
    return floorf((q0 * 19595.0f + q1 * 38470.0f + q2 * 7471.0f + 32768.0f) * (1.0f / 65536.0f));
}

__device__ __forceinline__ unsigned packh2(float a, float b) {
    __half2 h = __floats2half2_rn(a, b);
    return *reinterpret_cast<unsigned*>(&h);
}
__device__ __forceinline__ float2 unpackh2(unsigned u) {
    __half2 h = *reinterpret_cast<__half2*>(&u);
    return __half22float2(h);
}

// Software grid barrier. All NCTA CTAs are guaranteed co-resident:
// launch_bounds(512,2) caps regs at 64, dyn smem 96256B -> exactly 2 CTAs/SM,
// 2*148 = 296 = NCTA (152 SMs on GB300: even more headroom).
__device__ __forceinline__ void gridbar(unsigned target) {
    __syncthreads();
    if (threadIdx.x == 0) {
        __threadfence();                       // release all prior writes
        atomicAdd(&g_bar, 1u);
        while (*(volatile unsigned*)&g_bar < target) { }
    }
    __syncthreads();
    __threadfence();                           // acquire
}

__device__ __forceinline__ float interp1(float x, float gmin, float scale, const float* cdf) {
    float u = (x - gmin) * scale;
    int k = (int)u;
    if (k >= 255) return cdf[255];
    float f = u - (float)k;
    return cdf[k] + (cdf[k + 1] - cdf[k]) * f;
}

__global__ __launch_bounds__(NTHR, 2) void kmain(const float4* __restrict__ in,
                                                 const float4* __restrict__ Rp,
                                                 const float4* __restrict__ Lp,
                                                 float* __restrict__ out) {
    extern __shared__ char sm[];
    float4*   s_im  = (float4*)sm;
    uint2*    s_rm  = (uint2*)(sm + MAXR*512*16);
    float*    s_lut = (float*)(sm + MAXR*512*24);
    float*    s_cdf = s_lut + 256;
    unsigned* s_h   = (unsigned*)(s_cdf + 256);
    __shared__ double redd[3][16];
    __shared__ float  redf[2][16];

    const int tid = threadIdx.x;
    const int cta = blockIdx.x;

    // row slab: CTAs 0..271 get 7 rows, 272..295 get 6 rows (272*7 + 24*6 = 2048)
    int nr, r0;
    if (cta < 272) { nr = 7; r0 = cta * 7; }
    else           { nr = 6; r0 = 1904 + (cta - 272) * 6; }

    for (int i = tid; i < 256; i += NTHR)
        s_lut[i] = __expf((float)i * (-10.0f / 255.0f));
    __syncthreads();

    // ---------------- Phase 1: fused per-pixel pass ----------------
    const int col = tid;                      // float4 column 0..511
    float4 gP, lP;
    if (r0 == 0) {
        gP = make_float4(0.f, 0.f, 0.f, 0.f);
        lP = gP;
    } else {
        int idx = (r0 - 1) * W4 + col;
        float4 b0 = Rp[idx], b1 = Rp[idx + HW4], b2 = Rp[idx + 2 * HW4];
        gP.x = grayc(b0.x, b1.x, b2.x);
        gP.y = grayc(b0.y, b1.y, b2.y);
        gP.z = grayc(b0.z, b1.z, b2.z);
        gP.w = grayc(b0.w, b1.w, b2.w);
        lP = Lp[idx];
    }

    double sRec = 0.0, sRs = 0.0, sIs = 0.0;
    float vmin = 3.0f, vmax = -1.0f;

    #pragma unroll 1
    for (int rr = 0; rr < nr; rr++) {
        int idx = (r0 + rr) * W4 + col;
        float4 a0 = in[idx], a1 = in[idx + HW4], a2 = in[idx + 2 * HW4];
        float4 b0 = Rp[idx], b1 = Rp[idx + HW4], b2 = Rp[idx + 2 * HW4];
        float4 lv = Lp[idx];

        float rec =
            fabsf(b0.x * lv.x - a0.x) + fabsf(b0.y * lv.y - a0.y) +
            fabsf(b0.z * lv.z - a0.z) + fabsf(b0.w * lv.w - a0.w) +
            fabsf(b1.x * lv.x - a1.x) + fabsf(b1.y * lv.y - a1.y) +
            fabsf(b1.z * lv.z - a1.z) + fabsf(b1.w * lv.w - a1.w) +
            fabsf(b2.x * lv.x - a2.x) + fabsf(b2.y * lv.y - a2.y) +
            fabsf(b2.z * lv.z - a2.z) + fabsf(b2.w * lv.w - a2.w);

        float4 im, rm, g;
        im.x = fmaxf(a0.x, fmaxf(a1.x, a2.x));
        im.y = fmaxf(a0.y, fmaxf(a1.y, a2.y));
        im.z = fmaxf(a0.z, fmaxf(a1.z, a2.z));
        im.w = fmaxf(a0.w, fmaxf(a1.w, a2.w));
        rm.x = fmaxf(b0.x, fmaxf(b1.x, b2.x));
        rm.y = fmaxf(b0.y, fmaxf(b1.y, b2.y));
        rm.z = fmaxf(b0.z, fmaxf(b1.z, b2.z));
        rm.w = fmaxf(b0.w, fmaxf(b1.w, b2.w));

        int li = rr * 512 + col;
        s_im[li] = im;
        s_rm[li] = make_uint2(packh2(rm.x, rm.y), packh2(rm.z, rm.w));

        vmin = fminf(vmin, fminf(fminf(im.x, im.y), fminf(im.z, im.w)));
        vmax = fmaxf(vmax, fmaxf(fmaxf(im.x, im.y), fmaxf(im.z, im.w)));

        g.x = grayc(b0.x, b1.x, b2.x);
        g.y = grayc(b0.y, b1.y, b2.y);
        g.z = grayc(b0.z, b1.z, b2.z);
        g.w = grayc(b0.w, b1.w, b2.w);

        float rs = 0.f, is = 0.f;
        {
            float dg = fabsf(g.x - gP.x);
            rs += dg + 2.0f * g.x;
            is += fabsf(lv.x - lP.x) * s_lut[(int)dg] + 2.0f * fabsf(lv.x) * s_lut[(int)g.x];
        }
        {
            float dg = fabsf(g.y - gP.y);
            rs += dg + 2.0f * g.y;
            is += fabsf(lv.y - lP.y) * s_lut[(int)dg] + 2.0f * fabsf(lv.y) * s_lut[(int)g.y];
        }
        {
            float dg = fabsf(g.z - gP.z);
            rs += dg + 2.0f * g.z;
            is += fabsf(lv.z - lP.z) * s_lut[(int)dg] + 2.0f * fabsf(lv.z) * s_lut[(int)g.z];
        }
        {
            float dg = fabsf(g.w - gP.w);
            rs += dg + 2.0f * g.w;
            is += fabsf(lv.w - lP.w) * s_lut[(int)dg] + 2.0f * fabsf(lv.w) * s_lut[(int)g.w];
        }
        sRec += (double)rec;
        sRs  += (double)rs;
        sIs  += (double)is;
        gP = g;
        lP = lv;
    }

    if (r0 + nr == HH) {   // bottom padded edge
        float rs = gP.x + gP.y + gP.z + gP.w;
        float is = fabsf(lP.x) * s_lut[(int)gP.x] + fabsf(lP.y) * s_lut[(int)gP.y] +
                   fabsf(lP.z) * s_lut[(int)gP.z] + fabsf(lP.w) * s_lut[(int)gP.w];
        sRs += (double)rs;
        sIs += (double)is;
    }

    // block reduce (16 warps)
    const unsigned m = 0xffffffffu;
    for (int o = 16; o; o >>= 1) {
        sRec += __shfl_down_sync(m, sRec, o);
        sRs  += __shfl_down_sync(m, sRs,  o);
        sIs  += __shfl_down_sync(m, sIs,  o);
        vmin = fminf(vmin, __shfl_down_sync(m, vmin, o));
        vmax = fmaxf(vmax, __shfl_down_sync(m, vmax, o));
    }
    int lane = tid & 31, wid = tid >> 5;
    if (lane == 0) {
        redd[0][wid] = sRec; redd[1][wid] = sRs; redd[2][wid] = sIs;
        redf[0][wid] = vmin; redf[1][wid] = vmax;
    }
    __syncthreads();
    if (wid == 0) {
        sRec = (lane < 16) ? redd[0][lane] : 0.0;
        sRs  = (lane < 16) ? redd[1][lane] : 0.0;
        sIs  = (lane < 16) ? redd[2][lane] : 0.0;
        vmin = (lane < 16) ? redf[0][lane] : 3.0f;
        vmax = (lane < 16) ? redf[1][lane] : -1.0f;
        for (int o = 8; o; o >>= 1) {
            sRec += __shfl_down_sync(m, sRec, o);
            sRs  += __shfl_down_sync(m, sRs,  o);
            sIs  += __shfl_down_sync(m, sIs,  o);
            vmin = fminf(vmin, __shfl_down_sync(m, vmin, o));
            vmax = fmaxf(vmax, __shfl_down_sync(m, vmax, o));
        }
        if (lane == 0) {
            atomicAdd(&g_sums[0], sRec);
            atomicAdd(&g_sums[1], sRs);
            atomicAdd(&g_sums[2], sIs);
            atomicMin(&g_minbits, __float_as_int(vmin));
            atomicMax(&g_maxbits, __float_as_int(vmax));
        }
    }

    gridbar(NCTA);

    // ---------------- Phase 2: histogram from smem ----------------
    const float gmin = __int_as_float(__ldcg(&g_minbits));
    const float gmax = __int_as_float(__ldcg(&g_maxbits));
    const float scale = 256.0f / (gmax - gmin);

    for (int i = tid; i < 256 * SUB; i += NTHR) s_h[i] = 0u;
    __syncthreads();
    const unsigned sub = tid & (SUB - 1);
    const int nelem = nr * 512;
    for (int i = tid; i < nelem; i += NTHR) {
        float4 v = s_im[i];
        int k0 = min(255, (int)((v.x - gmin) * scale));
        int k1 = min(255, (int)((v.y - gmin) * scale));
        int k2 = min(255, (int)((v.z - gmin) * scale));
        int k3 = min(255, (int)((v.w - gmin) * scale));
        atomicAdd(&s_h[k0 * SUB + sub], 1u);
        atomicAdd(&s_h[k1 * SUB + sub], 1u);
        atomicAdd(&s_h[k2 * SUB + sub], 1u);
        atomicAdd(&s_h[k3 * SUB + sub], 1u);
    }
    __syncthreads();
    if (tid < 256) {
        unsigned s = 0;
        #pragma unroll
        for (int j = 0; j < SUB; j++) s += s_h[tid * SUB + j];
        if (s) atomicAdd(&g_hist[tid], s);
    }

    gridbar(2 * NCTA);

    // ---------------- Phase 3: cdf scan + interp + eq-sum ----------------
    if (tid < 256) s_cdf[tid] = (float)__ldcg(&g_hist[tid]);   // counts sum to 2^22: exact in fp32
    __syncthreads();
    for (int off = 1; off < 256; off <<= 1) {
        float t = 0.0f;
        if (tid < 256 && tid >= off) t = s_cdf[tid - off];
        __syncthreads();
        if (tid < 256) s_cdf[tid] += t;
        __syncthreads();
    }
    float norm = s_cdf[255];
    __syncthreads();
    if (tid < 256) s_cdf[tid] = s_cdf[tid] / norm;
    __syncthreads();

    double sEq = 0.0;
    for (int i = tid; i < nelem; i += NTHR) {
        float4 v = s_im[i];
        uint2 ru = s_rm[i];
        float2 rlo = unpackh2(ru.x);
        float2 rhi = unpackh2(ru.y);
        float t = fabsf(rlo.x - interp1(v.x, gmin, scale, s_cdf))
                + fabsf(rlo.y - interp1(v.y, gmin, scale, s_cdf))
                + fabsf(rhi.x - interp1(v.z, gmin, scale, s_cdf))
                + fabsf(rhi.y - interp1(v.w, gmin, scale, s_cdf));
        sEq += (double)t;
    }
    for (int o = 16; o; o >>= 1) sEq += __shfl_down_sync(m, sEq, o);
    if (lane == 0) redd[0][wid] = sEq;
    __syncthreads();
    if (wid == 0) {
        sEq = (lane < 16) ? redd[0][lane] : 0.0;
        for (int o = 8; o; o >>= 1) sEq += __shfl_down_sync(m, sEq, o);
        if (lane == 0) atomicAdd(&g_sums[3], sEq);
    }

    gridbar(3 * NCTA);

    // ---------------- Final combine ----------------
    if (cta == 0 && tid == 0) {
        double recon = __ldcg(&g_sums[0]) / (3.0 * (double)HWN);
        double denom = 2.0 * (double)(HH + 1) * (double)(WW + 2);
        double rs = __ldcg(&g_sums[1]) / (255.0 * denom);
        double is = __ldcg(&g_sums[2]) / denom;
        double eq = __ldcg(&g_sums[3]) / (double)HWN;
        out[0] = (float)(recon + 0.1 * is + 0.1 * eq + 0.01 * rs);
    }
}

extern "C" void kernel_launch(void* const* d_in, const int* in_sizes, int n_in,
                              void* d_out, int out_size) {
    const float4* in = (const float4*)d_in[0];
    const float4* Rp = (const float4*)d_in[1];
    const float4* Lp = (const float4*)d_in[2];
    (void)in_sizes; (void)n_in; (void)out_size;

    cudaFuncSetAttribute(kmain, cudaFuncAttributeMaxDynamicSharedMemorySize, SMEM_BYTES);

    k_zero<<<1, 256>>>();
    kmain<<<NCTA, NTHR, SMEM_BYTES>>>(in, Rp, Lp, (float*)d_out);
}